// round 14
// baseline (speedup 1.0000x reference)
#include <cuda_runtime.h>
#include <cuda_bf16.h>
#include <cstdint>
#include <math.h>

// Problem constants
#define BATCH  8
#define C_IN   256
#define NPIX   1024   // 32*32
#define INNER  512
#define HEADS  8
#define DH     64
#define KCONV  2304   // 256*9
#define MKV    1024

// ---------------------------------------------------------------------------
// bf16 hi/lo PLANE format: v ~ hi + lo (hi = bf16(v), lo = bf16(v - hi)).
// Separate hi/lo arrays -> every tile fill is a contiguous 16B cp.async.
// Wkv is stored PERMUTED: k' = tap*256 + ci (tap-major), enabling the conv
// to run as 9 shifted 1x1 GEMMs directly on XT (no im2col materialization).
// ---------------------------------------------------------------------------
__device__ uint16_t g_Wq_h [(size_t)INNER * C_IN],  g_Wq_l [(size_t)INNER * C_IN];
__device__ uint16_t g_Wkv_h[(size_t)MKV * KCONV],   g_Wkv_l[(size_t)MKV * KCONV];
__device__ uint16_t g_Wo_h [(size_t)C_IN * INNER],  g_Wo_l [(size_t)C_IN * INNER];
__device__ uint16_t g_XT_h [(size_t)BATCH * NPIX * C_IN];   // x^T [b][pix][ci]
__device__ uint16_t g_XT_l [(size_t)BATCH * NPIX * C_IN];
__device__ uint16_t g_QT_h [(size_t)BATCH * NPIX * INNER];  // Q^T [b][pix][hd]
__device__ uint16_t g_QT_l [(size_t)BATCH * NPIX * INNER];
__device__ uint16_t g_KT_h [(size_t)BATCH * NPIX * INNER];  // K^T [b][pix][hd]
__device__ uint16_t g_KT_l [(size_t)BATCH * NPIX * INNER];
__device__ uint16_t g_V_h  [(size_t)BATCH * INNER * NPIX];  // V   [b][hd][pix]
__device__ uint16_t g_V_l  [(size_t)BATCH * INNER * NPIX];
__device__ uint16_t g_AOT_h[(size_t)BATCH * NPIX * INNER];  // gelu(attn)^T
__device__ uint16_t g_AOT_l[(size_t)BATCH * NPIX * INNER];

__device__ __forceinline__ void split2(float v, __nv_bfloat16& h, __nv_bfloat16& l) {
    h = __float2bfloat16(v);
    l = __float2bfloat16(v - __bfloat162float(h));
}
__device__ __forceinline__ uint16_t u16(__nv_bfloat16 x) { return __bfloat16_as_ushort(x); }

// ===========================================================================
// mma.sync / ldmatrix / cp.async helpers (plain sm_103 — tcgen05 is 'a'-only)
// ===========================================================================
__device__ __forceinline__ uint32_t smem_u32(const void* p) {
    uint32_t a;
    asm("{ .reg .u64 t; cvta.to.shared.u64 t, %1; cvt.u32.u64 %0, t; }"
        : "=r"(a) : "l"(p));
    return a;
}
__device__ __forceinline__ void ldmx4(uint32_t* r, uint32_t addr) {
    asm volatile("ldmatrix.sync.aligned.m8n8.x4.shared.b16 {%0,%1,%2,%3}, [%4];"
        : "=r"(r[0]), "=r"(r[1]), "=r"(r[2]), "=r"(r[3]) : "r"(addr));
}
__device__ __forceinline__ void mma_bf16(float* c, const uint32_t* a,
                                         uint32_t b0, uint32_t b1) {
    asm volatile(
        "mma.sync.aligned.m16n8k16.row.col.f32.bf16.bf16.f32 "
        "{%0,%1,%2,%3}, {%4,%5,%6,%7}, {%8,%9}, {%0,%1,%2,%3};"
        : "+f"(c[0]), "+f"(c[1]), "+f"(c[2]), "+f"(c[3])
        : "r"(a[0]), "r"(a[1]), "r"(a[2]), "r"(a[3]), "r"(b0), "r"(b1));
}
__device__ __forceinline__ void cp16(uint32_t dst, const void* src) {
    asm volatile("cp.async.cg.shared.global [%0], [%1], 16;" :: "r"(dst), "l"(src));
}
__device__ __forceinline__ void cp16z(uint32_t dst, const void* src, uint32_t bytes) {
    asm volatile("cp.async.cg.shared.global [%0], [%1], 16, %2;"
        :: "r"(dst), "l"(src), "r"(bytes));
}
#define CP_COMMIT() asm volatile("cp.async.commit_group;")
#define CP_WAIT1()  asm volatile("cp.async.wait_group 1;")
#define CP_WAIT0()  asm volatile("cp.async.wait_group 0;")

#define ASTR 72   // smem row stride in halfwords (144B): conflict-free ldmatrix

// ===========================================================================
// prep kernels: weight splits (Wkv permuted tap-major) + XT transpose
// ===========================================================================
__global__ __launch_bounds__(256)
void split_planes(const float* __restrict__ in, uint16_t* __restrict__ oh,
                  uint16_t* __restrict__ ol, int n, float scale)
{
    int i = blockIdx.x * 256 + threadIdx.x;
    if (i < n) {
        float v = in[i] * scale;
        __nv_bfloat16 h, l; split2(v, h, l);
        oh[i] = u16(h); ol[i] = u16(l);
    }
}

__global__ __launch_bounds__(256)
void split_wkv_perm(const float* __restrict__ in, uint16_t* __restrict__ oh,
                    uint16_t* __restrict__ ol)
{
    int i = blockIdx.x * 256 + threadIdx.x;
    if (i < MKV * KCONV) {
        int co = i / KCONV, r = i - co * KCONV;   // r = tap*256 + ci (output order)
        int tap = r >> 8, ci = r & 255;
        float v = in[(size_t)co * KCONV + ci * 9 + tap];
        __nv_bfloat16 h, l; split2(v, h, l);
        oh[i] = u16(h); ol[i] = u16(l);
    }
}

__global__ __launch_bounds__(256)
void transXT(const float* __restrict__ x, uint16_t* __restrict__ XTh,
             uint16_t* __restrict__ XTl)
{
    __shared__ float tile[32][33];
    int tx = threadIdx.x & 31, ty = threadIdx.x >> 5;
    int p0 = blockIdx.x * 32, c0 = blockIdx.y * 32, b = blockIdx.z;
    const float* xb = x + (size_t)b * C_IN * NPIX;
    #pragma unroll
    for (int r = 0; r < 4; r++)
        tile[ty * 4 + r][tx] = xb[(size_t)(c0 + ty * 4 + r) * NPIX + p0 + tx];
    __syncthreads();
    #pragma unroll
    for (int r = 0; r < 4; r++) {
        int pix = p0 + ty * 4 + r;
        float v = tile[tx][ty * 4 + r];
        __nv_bfloat16 h, l; split2(v, h, l);
        size_t o = ((size_t)b * NPIX + pix) * C_IN + c0 + tx;
        XTh[o] = u16(h); XTl[o] = u16(l);
    }
}

// ===========================================================================
// Generic plane GEMM, cp.async double-buffered, CTA 128m x 128n:
//   C[b][m][n] = sum_k A[m][k] * B[b][n][k]
// TAPS=1 (conv): panel = (tap, ci-group); B rows come from XT at the
// tap-shifted pixel, zero-filled outside the image.
// EPI: 0 -> transposed planes [b][n][m] (QT);
//      1 -> m0<512: KT planes, else V planes;  2 -> float + bias.
// smem/buffer: Ah 18432 | Al 18432 | Bh 18432 | Bl 18432 = 73728 B, x2 buf.
// ===========================================================================
#define GP_BUF  73728
#define GP_SMEM (2 * GP_BUF)   // 147456 B

template<int TAPS>
__device__ __forceinline__ void gp_fill(
    uint32_t ub, int t, int panel, int m0, int n0, int K,
    const uint16_t* __restrict__ Ah, const uint16_t* __restrict__ Al,
    const uint16_t* __restrict__ Bh, const uint16_t* __restrict__ Bl)
{
    const int k0 = panel * 64;
    #pragma unroll
    for (int r = 0; r < 8; r++) {
        int c = t + r * 256;
        int row = c >> 4, sub = c & 15, pl = sub >> 3, col = sub & 7;
        const uint16_t* s = (pl ? Al : Ah) + (size_t)(m0 + row) * K + k0 + col * 8;
        cp16(ub + pl * 18432 + row * 144 + col * 16, s);
    }
    if (TAPS == 0) {
        #pragma unroll
        for (int r = 0; r < 8; r++) {
            int c = t + r * 256;
            int row = c >> 4, sub = c & 15, pl = sub >> 3, col = sub & 7;
            const uint16_t* s = (pl ? Bl : Bh) + (size_t)(n0 + row) * K + k0 + col * 8;
            cp16(ub + 36864 + pl * 18432 + row * 144 + col * 16, s);
        }
    } else {
        int tap = panel >> 2, cig = panel & 3;
        int dy = tap / 3 - 1, dx = tap - (tap / 3) * 3 - 1;
        #pragma unroll
        for (int r = 0; r < 8; r++) {
            int c = t + r * 256;
            int row = c >> 4, sub = c & 15, pl = sub >> 3, col = sub & 7;
            int p = n0 + row;
            int y = (p >> 5) + dy, x = (p & 31) + dx;
            bool ok = ((unsigned)y < 32u) && ((unsigned)x < 32u);
            size_t sp = (size_t)(ok ? ((y << 5) + x) : 0) * C_IN + cig * 64 + col * 8;
            const uint16_t* s = (pl ? Bl : Bh) + sp;
            cp16z(ub + 36864 + pl * 18432 + row * 144 + col * 16, s, ok ? 16u : 0u);
        }
    }
}

template<int EPI, int TAPS>
__global__ __launch_bounds__(256)
void gemm_planes(const uint16_t* __restrict__ Ah, const uint16_t* __restrict__ Al,
                 const uint16_t* __restrict__ Bh, const uint16_t* __restrict__ Bl,
                 int K, int NP,
                 uint16_t* __restrict__ Oth, uint16_t* __restrict__ Otl,
                 uint16_t* __restrict__ Ovh, uint16_t* __restrict__ Ovl,
                 float* __restrict__ Of, const float* __restrict__ bias, int M)
{
    extern __shared__ char smem[];
    const uint32_t us = smem_u32(smem);
    const int t = threadIdx.x;
    const int warp = t >> 5, lane = t & 31;
    const int wm = warp & 3, wn = warp >> 2;
    const int n0 = blockIdx.x * 128, m0 = blockIdx.y * 128;
    const int b  = blockIdx.z;
    const uint16_t* Bhb = Bh + (size_t)b * NPIX * (TAPS ? C_IN : K);
    const uint16_t* Blb = Bl + (size_t)b * NPIX * (TAPS ? C_IN : K);

    const int arow  = lane & 15;
    const int acolb = (lane >> 4) * 16;
    const int brow  = (lane & 7) + ((lane >> 4) << 3);
    const int bcolb = ((lane >> 3) & 1) * 16;

    float acc[2][8][4] = {};

    gp_fill<TAPS>(us, t, 0, m0, n0, K, Ah, Al, Bhb, Blb);
    CP_COMMIT();
    for (int p = 0; p < NP; p++) {
        if (p + 1 < NP) {
            gp_fill<TAPS>(us + ((p + 1) & 1) * GP_BUF, t, p + 1, m0, n0, K,
                          Ah, Al, Bhb, Blb);
            CP_COMMIT(); CP_WAIT1();
        } else { CP_WAIT0(); }
        __syncthreads();
        uint32_t ub  = us + (p & 1) * GP_BUF;
        uint32_t uAh = ub, uAl = ub + 18432, uBh = ub + 36864, uBl = ub + 55296;
        #pragma unroll
        for (int ks = 0; ks < 4; ks++) {
            const int kb = ks * 32;
            uint32_t ah[2][4], al[2][4], bh[4][4], bl[4][4];
            #pragma unroll
            for (int mt = 0; mt < 2; mt++) {
                uint32_t off = (uint32_t)((wm * 32 + mt * 16 + arow) * ASTR) * 2
                             + kb + acolb;
                ldmx4(ah[mt], uAh + off);
                ldmx4(al[mt], uAl + off);
            }
            #pragma unroll
            for (int nt2 = 0; nt2 < 4; nt2++) {
                uint32_t off = (uint32_t)((wn * 64 + nt2 * 16 + brow) * ASTR) * 2
                             + kb + bcolb;
                ldmx4(bh[nt2], uBh + off);
                ldmx4(bl[nt2], uBl + off);
            }
            #pragma unroll
            for (int mt = 0; mt < 2; mt++)
                #pragma unroll
                for (int nt = 0; nt < 8; nt++) {
                    uint32_t b0h = bh[nt >> 1][(nt & 1) * 2];
                    uint32_t b1h = bh[nt >> 1][(nt & 1) * 2 + 1];
                    uint32_t b0l = bl[nt >> 1][(nt & 1) * 2];
                    uint32_t b1l = bl[nt >> 1][(nt & 1) * 2 + 1];
                    mma_bf16(acc[mt][nt], ah[mt], b0h, b1h);
                    mma_bf16(acc[mt][nt], ah[mt], b0l, b1l);
                    mma_bf16(acc[mt][nt], al[mt], b0h, b1h);
                }
        }
        __syncthreads();
    }

    // stage fp32 result [128][132], then epilogue writeback
    float* sO = (float*)smem;
    #pragma unroll
    for (int mt = 0; mt < 2; mt++)
        #pragma unroll
        for (int nt = 0; nt < 8; nt++) {
            int row = wm * 32 + mt * 16 + (lane >> 2);
            int col = wn * 64 + nt * 8 + (lane & 3) * 2;
            *(float2*)(sO + row * 132 + col) =
                make_float2(acc[mt][nt][0], acc[mt][nt][1]);
            *(float2*)(sO + (row + 8) * 132 + col) =
                make_float2(acc[mt][nt][2], acc[mt][nt][3]);
        }
    __syncthreads();

    if (EPI == 0 || (EPI == 1 && m0 < 512)) {
        for (int i = t; i < 16384; i += 256) {
            int n = i >> 7, m = i & 127;
            __nv_bfloat16 h, l; split2(sO[m * 132 + n], h, l);
            size_t o = ((size_t)b * NPIX + n0 + n) * 512 + m0 + m;
            Oth[o] = u16(h); Otl[o] = u16(l);
        }
    } else if (EPI == 1) {
        for (int i = t; i < 16384; i += 256) {
            int m = i >> 7, n = i & 127;
            __nv_bfloat16 h, l; split2(sO[m * 132 + n], h, l);
            size_t o = ((size_t)b * INNER + (m0 - 512 + m)) * NPIX + n0 + n;
            Ovh[o] = u16(h); Ovl[o] = u16(l);
        }
    } else {
        for (int i = t; i < 16384; i += 256) {
            int m = i >> 7, n = i & 127;
            Of[((size_t)b * M + m0 + m) * NPIX + n0 + n] = sO[m * 132 + n] + bias[m0 + m];
        }
    }
}

// ===========================================================================
// Flash attention (unchanged from R13, validated): bf16x3 mma, cp.async
// K/V prefetch in separate commit groups, parallel softmax, fused GELU.
// ===========================================================================
#define FA_SMEM (8 * 9216 + 64 * 68 * 4 + 3 * 64 * 4)   // 91904 B

#define FA_FILLK(K0) do {                                                      \
    _Pragma("unroll")                                                          \
    for (int r_ = 0; r_ < 4; r_++) {                                           \
        int c_ = t + r_ * 256;                                                 \
        int row_ = c_ >> 4, sub_ = c_ & 15, pl_ = sub_ >> 3, col_ = sub_ & 7;  \
        cp16(uKh + pl_ * 9216 + row_ * 144 + col_ * 16,                        \
             (pl_ ? ksl : ksh) + (size_t)((K0) + row_) * INNER + col_ * 8);    \
    }                                                                          \
} while (0)
#define FA_FILLV(K0) do {                                                      \
    _Pragma("unroll")                                                          \
    for (int r_ = 0; r_ < 4; r_++) {                                           \
        int c_ = t + r_ * 256;                                                 \
        int row_ = c_ >> 4, sub_ = c_ & 15, pl_ = sub_ >> 3, col_ = sub_ & 7;  \
        cp16(uVh + pl_ * 9216 + row_ * 144 + col_ * 16,                        \
             (pl_ ? vsl : vsh) + (size_t)row_ * NPIX + (K0) + col_ * 8);       \
    }                                                                          \
} while (0)

__global__ __launch_bounds__(256)
void flash_attn_mma(const uint16_t* __restrict__ QTh, const uint16_t* __restrict__ QTl,
                    const uint16_t* __restrict__ KTh, const uint16_t* __restrict__ KTl,
                    const uint16_t* __restrict__ Vh,  const uint16_t* __restrict__ Vl,
                    uint16_t* __restrict__ AOTh, uint16_t* __restrict__ AOTl)
{
    extern __shared__ char smc[];
    const uint32_t base = smem_u32(smc);
    const uint32_t uQh = base,         uQl = base + 9216;
    const uint32_t uKh = base + 18432, uKl = base + 27648;
    const uint32_t uVh = base + 36864, uVl = base + 46080;
    const uint32_t uPh = base + 55296, uPl = base + 64512;
    uint16_t* sPh = (uint16_t*)(smc + 55296);
    uint16_t* sPl = (uint16_t*)(smc + 64512);
    float* sS = (float*)(smc + 73728);   // [64][68]
    float* rm = sS + 64 * 68;
    float* rl = rm + 64;
    float* rf = rl + 64;

    const int t    = threadIdx.x;
    const int warp = t >> 5, lane = t & 31;
    const int wm   = warp & 3, wn = warp >> 2;
    const int q0   = blockIdx.x * 64;
    const int bh   = blockIdx.y;
    const int b    = bh >> 3, h = bh & 7;

    const uint16_t* qsh = QTh + ((size_t)b * NPIX + q0) * INNER + h * 64;
    const uint16_t* qsl = QTl + ((size_t)b * NPIX + q0) * INNER + h * 64;
    const uint16_t* ksh = KTh + (size_t)b * NPIX * INNER + h * 64;
    const uint16_t* ksl = KTl + (size_t)b * NPIX * INNER + h * 64;
    const uint16_t* vsh = Vh + ((size_t)b * INNER + h * 64) * NPIX;
    const uint16_t* vsl = Vl + ((size_t)b * INNER + h * 64) * NPIX;

    const int arow  = lane & 15;
    const int acolb = (lane >> 4) * 16;
    const int brow  = (lane & 7) + ((lane >> 4) << 3);
    const int bcolb = ((lane >> 3) & 1) * 16;

    #pragma unroll
    for (int r = 0; r < 4; r++) {
        int c = t + r * 256;
        int row = c >> 4, sub = c & 15, pl = sub >> 3, col = sub & 7;
        cp16(uQh + pl * 9216 + row * 144 + col * 16,
             (pl ? qsl : qsh) + (size_t)row * INNER + col * 8);
    }
    FA_FILLK(0); CP_COMMIT();
    FA_FILLV(0); CP_COMMIT();
    if (t < 64) { rm[t] = -1e30f; rl[t] = 0.f; }

    float accO[4][4] = {};

    for (int kt = 0; kt < 16; kt++) {
        CP_WAIT1();
        __syncthreads();

        float s[4][4] = {};
        #pragma unroll
        for (int ks = 0; ks < 4; ks++) {
            const int kbyte = ks * 32;
            uint32_t ah[4], al[4], bhv[2][4], blv[2][4];
            {
                uint32_t off = (uint32_t)((wm * 16 + arow) * ASTR) * 2 + kbyte + acolb;
                ldmx4(ah, uQh + off);
                ldmx4(al, uQl + off);
            }
            #pragma unroll
            for (int nt2 = 0; nt2 < 2; nt2++) {
                uint32_t off = (uint32_t)((wn * 32 + nt2 * 16 + brow) * ASTR) * 2
                             + kbyte + bcolb;
                ldmx4(bhv[nt2], uKh + off);
                ldmx4(blv[nt2], uKl + off);
            }
            #pragma unroll
            for (int nt = 0; nt < 4; nt++) {
                uint32_t b0h = bhv[nt >> 1][(nt & 1) * 2];
                uint32_t b1h = bhv[nt >> 1][(nt & 1) * 2 + 1];
                uint32_t b0l = blv[nt >> 1][(nt & 1) * 2];
                uint32_t b1l = blv[nt >> 1][(nt & 1) * 2 + 1];
                mma_bf16(s[nt], ah, b0h, b1h);
                mma_bf16(s[nt], ah, b0l, b1l);
                mma_bf16(s[nt], al, b0h, b1h);
            }
        }
        {
            int row = wm * 16 + (lane >> 2);
            #pragma unroll
            for (int nt = 0; nt < 4; nt++) {
                int col = wn * 32 + nt * 8 + (lane & 3) * 2;
                *(float2*)(sS + row * 68 + col)       = make_float2(s[nt][0], s[nt][1]);
                *(float2*)(sS + (row + 8) * 68 + col) = make_float2(s[nt][2], s[nt][3]);
            }
        }
        __syncthreads();

        if (kt < 15) { FA_FILLK((kt + 1) * 64); CP_COMMIT(); }

        {
            int r  = t >> 2;
            int c0 = (t & 3) * 16;
            float mo = rm[r];
            float mx = mo;
            #pragma unroll
            for (int j = 0; j < 16; j++) mx = fmaxf(mx, sS[r * 68 + c0 + j]);
            mx = fmaxf(mx, __shfl_xor_sync(0xffffffffu, mx, 1));
            mx = fmaxf(mx, __shfl_xor_sync(0xffffffffu, mx, 2));
            float sum = 0.f;
            #pragma unroll
            for (int j = 0; j < 16; j++) {
                float e = __expf(sS[r * 68 + c0 + j] - mx);
                sum += e;
                __nv_bfloat16 hh, ll; split2(e, hh, ll);
                sPh[r * ASTR + c0 + j] = u16(hh);
                sPl[r * ASTR + c0 + j] = u16(ll);
            }
            sum += __shfl_xor_sync(0xffffffffu, sum, 1);
            sum += __shfl_xor_sync(0xffffffffu, sum, 2);
            if ((t & 3) == 0) {
                float f = __expf(mo - mx);
                rf[r] = f;
                rl[r] = rl[r] * f + sum;
                rm[r] = mx;
            }
        }
        if (kt < 15) { CP_WAIT1(); } else { CP_WAIT0(); }
        __syncthreads();

        {
            float f0 = rf[wm * 16 + (lane >> 2)];
            float f1 = rf[wm * 16 + (lane >> 2) + 8];
            #pragma unroll
            for (int nt = 0; nt < 4; nt++) {
                accO[nt][0] *= f0; accO[nt][1] *= f0;
                accO[nt][2] *= f1; accO[nt][3] *= f1;
            }
        }
        #pragma unroll
        for (int ks = 0; ks < 4; ks++) {
            const int kbyte = ks * 32;
            uint32_t ph[4], pl[4], bhv[2][4], blv[2][4];
            {
                uint32_t off = (uint32_t)((wm * 16 + arow) * ASTR) * 2 + kbyte + acolb;
                ldmx4(ph, uPh + off);
                ldmx4(pl, uPl + off);
            }
            #pragma unroll
            for (int nt2 = 0; nt2 < 2; nt2++) {
                uint32_t off = (uint32_t)((wn * 32 + nt2 * 16 + brow) * ASTR) * 2
                             + kbyte + bcolb;
                ldmx4(bhv[nt2], uVh + off);
                ldmx4(blv[nt2], uVl + off);
            }
            #pragma unroll
            for (int nt = 0; nt < 4; nt++) {
                uint32_t b0h = bhv[nt >> 1][(nt & 1) * 2];
                uint32_t b1h = bhv[nt >> 1][(nt & 1) * 2 + 1];
                uint32_t b0l = blv[nt >> 1][(nt & 1) * 2];
                uint32_t b1l = blv[nt >> 1][(nt & 1) * 2 + 1];
                mma_bf16(accO[nt], ph, b0h, b1h);
                mma_bf16(accO[nt], ph, b0l, b1l);
                mma_bf16(accO[nt], pl, b0h, b1h);
            }
        }
        __syncthreads();
        if (kt < 15) { FA_FILLV((kt + 1) * 64); CP_COMMIT(); }
    }

    {
        int row0 = wm * 16 + (lane >> 2);
        float i0 = 1.f / rl[row0];
        float i1 = 1.f / rl[row0 + 8];
        #pragma unroll
        for (int nt = 0; nt < 4; nt++) {
            int col = wn * 32 + nt * 8 + (lane & 3) * 2;
            #pragma unroll
            for (int e = 0; e < 4; e++) {
                float v = accO[nt][e] * (e < 2 ? i0 : i1);
                float g = 0.5f * v * (1.f + erff(v * 0.70710678118654752f));
                sS[(row0 + (e >> 1) * 8) * 68 + col + (e & 1)] = g;
            }
        }
    }
    __syncthreads();
    for (int idx = t; idx < 4096; idx += 256) {
        int q = idx >> 6, d = idx & 63;
        __nv_bfloat16 hh, ll; split2(sS[q * 68 + d], hh, ll);
        size_t o = ((size_t)b * NPIX + q0 + q) * INNER + h * 64 + d;
        AOTh[o] = u16(hh); AOTl[o] = u16(ll);
    }
}

// ---------------------------------------------------------------------------
extern "C" void kernel_launch(void* const* d_in, const int* in_sizes, int n_in,
                              void* d_out, int out_size)
{
    const float* x    = (const float*)d_in[0];
    const float* Wq   = (const float*)d_in[1];
    const float* Wkv  = (const float*)d_in[2];
    const float* Wout = (const float*)d_in[3];
    const float* bout = (const float*)d_in[4];
    float* out = (float*)d_out;

    uint16_t *wqh, *wql, *wkvh, *wkvl, *woh, *wol;
    uint16_t *xth, *xtl, *qth, *qtl, *kth, *ktl, *vh, *vl, *aoh, *aol;
    cudaGetSymbolAddress((void**)&wqh,  g_Wq_h);  cudaGetSymbolAddress((void**)&wql,  g_Wq_l);
    cudaGetSymbolAddress((void**)&wkvh, g_Wkv_h); cudaGetSymbolAddress((void**)&wkvl, g_Wkv_l);
    cudaGetSymbolAddress((void**)&woh,  g_Wo_h);  cudaGetSymbolAddress((void**)&wol,  g_Wo_l);
    cudaGetSymbolAddress((void**)&xth,  g_XT_h);  cudaGetSymbolAddress((void**)&xtl,  g_XT_l);
    cudaGetSymbolAddress((void**)&qth,  g_QT_h);  cudaGetSymbolAddress((void**)&qtl,  g_QT_l);
    cudaGetSymbolAddress((void**)&kth,  g_KT_h);  cudaGetSymbolAddress((void**)&ktl,  g_KT_l);
    cudaGetSymbolAddress((void**)&vh,   g_V_h);   cudaGetSymbolAddress((void**)&vl,   g_V_l);
    cudaGetSymbolAddress((void**)&aoh,  g_AOT_h); cudaGetSymbolAddress((void**)&aol,  g_AOT_l);

    dim3 blk(256);

    // 0) weight planes (Wq scale-folded; Wkv tap-major permuted) + XT
    split_planes<<<(INNER * C_IN + 255) / 256, blk>>>(Wq, wqh, wql, INNER * C_IN, 0.125f);
    split_wkv_perm<<<(MKV * KCONV + 255) / 256, blk>>>(Wkv, wkvh, wkvl);
    split_planes<<<(C_IN * INNER + 255) / 256, blk>>>(Wout, woh, wol, C_IN * INNER, 1.f);
    transXT<<<dim3(32, 8, BATCH), blk>>>(x, xth, xtl);

    // 1) Q^T = (Wq/8 · x)^T   (K=256, 4 panels)
    cudaFuncSetAttribute(gemm_planes<0,0>, cudaFuncAttributeMaxDynamicSharedMemorySize, GP_SMEM);
    gemm_planes<0,0><<<dim3(8, 4, BATCH), blk, GP_SMEM>>>(
        wqh, wql, xth, xtl, C_IN, 4, qth, qtl, nullptr, nullptr, nullptr, nullptr, INNER);

    // 2) KV = conv3x3 as 9 shifted 1x1 GEMMs on XT (36 panels)
    cudaFuncSetAttribute(gemm_planes<1,1>, cudaFuncAttributeMaxDynamicSharedMemorySize, GP_SMEM);
    gemm_planes<1,1><<<dim3(8, 8, BATCH), blk, GP_SMEM>>>(
        wkvh, wkvl, xth, xtl, KCONV, 36, kth, ktl, vh, vl, nullptr, nullptr, MKV);

    // 3) attention + GELU -> AOT planes
    cudaFuncSetAttribute(flash_attn_mma, cudaFuncAttributeMaxDynamicSharedMemorySize, FA_SMEM);
    flash_attn_mma<<<dim3(16, BATCH * HEADS), blk, FA_SMEM>>>(
        qth, qtl, kth, ktl, vh, vl, aoh, aol);

    // 4) out = Wout · gelu_attn + bout  (K=512, 8 panels)
    cudaFuncSetAttribute(gemm_planes<2,0>, cudaFuncAttributeMaxDynamicSharedMemorySize, GP_SMEM);
    gemm_planes<2,0><<<dim3(8, 2, BATCH), blk, GP_SMEM>>>(
        woh, wol, aoh, aol, INNER, 8, nullptr, nullptr, nullptr, nullptr, out, bout, 256);
}

// round 15
// speedup vs baseline: 1.2689x; 1.2689x over previous
#include <cuda_runtime.h>
#include <cuda_bf16.h>
#include <cstdint>
#include <math.h>

// Problem constants
#define BATCH  8
#define C_IN   256
#define NPIX   1024   // 32*32
#define INNER  512
#define HEADS  8
#define DH     64
#define KCONV  2304   // 256*9
#define MKV    1024

// ---------------------------------------------------------------------------
// bf16 hi/lo PLANE format: v ~ hi + lo. Wkv stored PERMUTED k' = tap*256+ci
// so the conv runs as 9 shifted 1x1 GEMMs on XT (no im2col materialization).
// ---------------------------------------------------------------------------
__device__ uint16_t g_Wq_h [(size_t)INNER * C_IN],  g_Wq_l [(size_t)INNER * C_IN];
__device__ uint16_t g_Wkv_h[(size_t)MKV * KCONV],   g_Wkv_l[(size_t)MKV * KCONV];
__device__ uint16_t g_Wo_h [(size_t)C_IN * INNER],  g_Wo_l [(size_t)C_IN * INNER];
__device__ uint16_t g_XT_h [(size_t)BATCH * NPIX * C_IN];
__device__ uint16_t g_XT_l [(size_t)BATCH * NPIX * C_IN];
__device__ uint16_t g_QT_h [(size_t)BATCH * NPIX * INNER];
__device__ uint16_t g_QT_l [(size_t)BATCH * NPIX * INNER];
__device__ uint16_t g_KT_h [(size_t)BATCH * NPIX * INNER];
__device__ uint16_t g_KT_l [(size_t)BATCH * NPIX * INNER];
__device__ uint16_t g_V_h  [(size_t)BATCH * INNER * NPIX];
__device__ uint16_t g_V_l  [(size_t)BATCH * INNER * NPIX];
__device__ uint16_t g_AOT_h[(size_t)BATCH * NPIX * INNER];
__device__ uint16_t g_AOT_l[(size_t)BATCH * NPIX * INNER];

__device__ __forceinline__ void split2(float v, __nv_bfloat16& h, __nv_bfloat16& l) {
    h = __float2bfloat16(v);
    l = __float2bfloat16(v - __bfloat162float(h));
}
__device__ __forceinline__ uint16_t u16(__nv_bfloat16 x) { return __bfloat16_as_ushort(x); }
// pack two values into hi-plane and lo-plane bf16x2 registers (MMA layout)
__device__ __forceinline__ void packsplit2(float a, float b, uint32_t& h, uint32_t& l) {
    __nv_bfloat16 ah, al, bh, bl;
    split2(a, ah, al); split2(b, bh, bl);
    h = (uint32_t)u16(ah) | ((uint32_t)u16(bh) << 16);
    l = (uint32_t)u16(al) | ((uint32_t)u16(bl) << 16);
}

// ===========================================================================
// mma.sync / ldmatrix / cp.async helpers (plain sm_103 — tcgen05 is 'a'-only)
// ===========================================================================
__device__ __forceinline__ uint32_t smem_u32(const void* p) {
    uint32_t a;
    asm("{ .reg .u64 t; cvta.to.shared.u64 t, %1; cvt.u32.u64 %0, t; }"
        : "=r"(a) : "l"(p));
    return a;
}
__device__ __forceinline__ void ldmx4(uint32_t* r, uint32_t addr) {
    asm volatile("ldmatrix.sync.aligned.m8n8.x4.shared.b16 {%0,%1,%2,%3}, [%4];"
        : "=r"(r[0]), "=r"(r[1]), "=r"(r[2]), "=r"(r[3]) : "r"(addr));
}
__device__ __forceinline__ void mma_bf16(float* c, const uint32_t* a,
                                         uint32_t b0, uint32_t b1) {
    asm volatile(
        "mma.sync.aligned.m16n8k16.row.col.f32.bf16.bf16.f32 "
        "{%0,%1,%2,%3}, {%4,%5,%6,%7}, {%8,%9}, {%0,%1,%2,%3};"
        : "+f"(c[0]), "+f"(c[1]), "+f"(c[2]), "+f"(c[3])
        : "r"(a[0]), "r"(a[1]), "r"(a[2]), "r"(a[3]), "r"(b0), "r"(b1));
}
__device__ __forceinline__ void cp16(uint32_t dst, const void* src) {
    asm volatile("cp.async.cg.shared.global [%0], [%1], 16;" :: "r"(dst), "l"(src));
}
__device__ __forceinline__ void cp16z(uint32_t dst, const void* src, uint32_t bytes) {
    asm volatile("cp.async.cg.shared.global [%0], [%1], 16, %2;"
        :: "r"(dst), "l"(src), "r"(bytes));
}
#define CP_COMMIT() asm volatile("cp.async.commit_group;")
#define CP_WAIT1()  asm volatile("cp.async.wait_group 1;")
#define CP_WAIT0()  asm volatile("cp.async.wait_group 0;")

#define ASTR 72   // smem row stride in halfwords (144B): conflict-free ldmatrix

// ===========================================================================
// prep kernels
// ===========================================================================
__global__ __launch_bounds__(256)
void split_planes(const float* __restrict__ in, uint16_t* __restrict__ oh,
                  uint16_t* __restrict__ ol, int n, float scale)
{
    int i = blockIdx.x * 256 + threadIdx.x;
    if (i < n) {
        float v = in[i] * scale;
        __nv_bfloat16 h, l; split2(v, h, l);
        oh[i] = u16(h); ol[i] = u16(l);
    }
}

__global__ __launch_bounds__(256)
void split_wkv_perm(const float* __restrict__ in, uint16_t* __restrict__ oh,
                    uint16_t* __restrict__ ol)
{
    int i = blockIdx.x * 256 + threadIdx.x;
    if (i < MKV * KCONV) {
        int co = i / KCONV, r = i - co * KCONV;   // r = tap*256 + ci
        int tap = r >> 8, ci = r & 255;
        float v = in[(size_t)co * KCONV + ci * 9 + tap];
        __nv_bfloat16 h, l; split2(v, h, l);
        oh[i] = u16(h); ol[i] = u16(l);
    }
}

__global__ __launch_bounds__(256)
void transXT(const float* __restrict__ x, uint16_t* __restrict__ XTh,
             uint16_t* __restrict__ XTl)
{
    __shared__ float tile[32][33];
    int tx = threadIdx.x & 31, ty = threadIdx.x >> 5;
    int p0 = blockIdx.x * 32, c0 = blockIdx.y * 32, b = blockIdx.z;
    const float* xb = x + (size_t)b * C_IN * NPIX;
    #pragma unroll
    for (int r = 0; r < 4; r++)
        tile[ty * 4 + r][tx] = xb[(size_t)(c0 + ty * 4 + r) * NPIX + p0 + tx];
    __syncthreads();
    #pragma unroll
    for (int r = 0; r < 4; r++) {
        int pix = p0 + ty * 4 + r;
        float v = tile[tx][ty * 4 + r];
        __nv_bfloat16 h, l; split2(v, h, l);
        size_t o = ((size_t)b * NPIX + pix) * C_IN + c0 + tx;
        XTh[o] = u16(h); XTl[o] = u16(l);
    }
}

// ===========================================================================
// Generic plane GEMM, cp.async double-buffered, CTA 128m x 64n (2 CTAs/SM):
//   C[b][m][n] = sum_k A[m][k] * B[b][n][k]
// TAPS=1: conv as 9 shifted 1x1 GEMMs on XT (panel = tap*4 + ci-group).
// Buffer: Ah 18432 | Al 18432 | Bh 9216 | Bl 9216 = 55296 B, x2.
// ===========================================================================
#define GP_BUF  55296
#define GP_SMEM (2 * GP_BUF)   // 110592 B -> 2 CTAs/SM

template<int TAPS>
__device__ __forceinline__ void gp_fill(
    uint32_t ub, int t, int panel, int m0, int n0, int K,
    const uint16_t* __restrict__ Ah, const uint16_t* __restrict__ Al,
    const uint16_t* __restrict__ Bh, const uint16_t* __restrict__ Bl)
{
    const int k0 = panel * 64;
    #pragma unroll
    for (int r = 0; r < 8; r++) {
        int c = t + r * 256;
        int row = c >> 4, sub = c & 15, pl = sub >> 3, col = sub & 7;
        cp16(ub + pl * 18432 + row * 144 + col * 16,
             (pl ? Al : Ah) + (size_t)(m0 + row) * K + k0 + col * 8);
    }
    if (TAPS == 0) {
        #pragma unroll
        for (int r = 0; r < 4; r++) {
            int c = t + r * 256;
            int row = c >> 4, sub = c & 15, pl = sub >> 3, col = sub & 7;
            cp16(ub + 36864 + pl * 9216 + row * 144 + col * 16,
                 (pl ? Bl : Bh) + (size_t)(n0 + row) * K + k0 + col * 8);
        }
    } else {
        int tap = panel >> 2, cig = panel & 3;
        int dy = tap / 3 - 1, dx = tap - (tap / 3) * 3 - 1;
        #pragma unroll
        for (int r = 0; r < 4; r++) {
            int c = t + r * 256;
            int row = c >> 4, sub = c & 15, pl = sub >> 3, col = sub & 7;
            int p = n0 + row;
            int y = (p >> 5) + dy, x = (p & 31) + dx;
            bool ok = ((unsigned)y < 32u) && ((unsigned)x < 32u);
            size_t sp = (size_t)(ok ? ((y << 5) + x) : 0) * C_IN + cig * 64 + col * 8;
            cp16z(ub + 36864 + pl * 9216 + row * 144 + col * 16,
                  (pl ? Bl : Bh) + sp, ok ? 16u : 0u);
        }
    }
}

template<int EPI, int TAPS>
__global__ __launch_bounds__(256)
void gemm_planes(const uint16_t* __restrict__ Ah, const uint16_t* __restrict__ Al,
                 const uint16_t* __restrict__ Bh, const uint16_t* __restrict__ Bl,
                 int K, int NP,
                 uint16_t* __restrict__ Oth, uint16_t* __restrict__ Otl,
                 uint16_t* __restrict__ Ovh, uint16_t* __restrict__ Ovl,
                 float* __restrict__ Of, const float* __restrict__ bias, int M)
{
    extern __shared__ char smem[];
    const uint32_t us = smem_u32(smem);
    const int t = threadIdx.x;
    const int warp = t >> 5, lane = t & 31;
    const int wm = warp & 3, wn = warp >> 2;
    const int n0 = blockIdx.x * 64, m0 = blockIdx.y * 128;
    const int b  = blockIdx.z;
    const uint16_t* Bhb = Bh + (size_t)b * NPIX * (TAPS ? C_IN : K);
    const uint16_t* Blb = Bl + (size_t)b * NPIX * (TAPS ? C_IN : K);

    const int arow  = lane & 15;
    const int acolb = (lane >> 4) * 16;
    const int brow  = (lane & 7) + ((lane >> 4) << 3);
    const int bcolb = ((lane >> 3) & 1) * 16;

    float acc[2][4][4] = {};

    gp_fill<TAPS>(us, t, 0, m0, n0, K, Ah, Al, Bhb, Blb);
    CP_COMMIT();
    for (int p = 0; p < NP; p++) {
        if (p + 1 < NP) {
            gp_fill<TAPS>(us + ((p + 1) & 1) * GP_BUF, t, p + 1, m0, n0, K,
                          Ah, Al, Bhb, Blb);
            CP_COMMIT(); CP_WAIT1();
        } else { CP_WAIT0(); }
        __syncthreads();
        uint32_t ub  = us + (p & 1) * GP_BUF;
        uint32_t uAh = ub, uAl = ub + 18432, uBh = ub + 36864, uBl = ub + 46080;
        #pragma unroll
        for (int ks = 0; ks < 4; ks++) {
            const int kb = ks * 32;
            uint32_t ah[2][4], al[2][4], bh[2][4], bl[2][4];
            #pragma unroll
            for (int mt = 0; mt < 2; mt++) {
                uint32_t off = (uint32_t)((wm * 32 + mt * 16 + arow) * ASTR) * 2
                             + kb + acolb;
                ldmx4(ah[mt], uAh + off);
                ldmx4(al[mt], uAl + off);
            }
            #pragma unroll
            for (int nt2 = 0; nt2 < 2; nt2++) {
                uint32_t off = (uint32_t)((wn * 32 + nt2 * 16 + brow) * ASTR) * 2
                             + kb + bcolb;
                ldmx4(bh[nt2], uBh + off);
                ldmx4(bl[nt2], uBl + off);
            }
            #pragma unroll
            for (int mt = 0; mt < 2; mt++)
                #pragma unroll
                for (int nt = 0; nt < 4; nt++) {
                    uint32_t b0h = bh[nt >> 1][(nt & 1) * 2];
                    uint32_t b1h = bh[nt >> 1][(nt & 1) * 2 + 1];
                    uint32_t b0l = bl[nt >> 1][(nt & 1) * 2];
                    uint32_t b1l = bl[nt >> 1][(nt & 1) * 2 + 1];
                    mma_bf16(acc[mt][nt], ah[mt], b0h, b1h);
                    mma_bf16(acc[mt][nt], ah[mt], b0l, b1l);
                    mma_bf16(acc[mt][nt], al[mt], b0h, b1h);
                }
        }
        __syncthreads();
    }

    float* sO = (float*)smem;   // [128][66]
    #pragma unroll
    for (int mt = 0; mt < 2; mt++)
        #pragma unroll
        for (int nt = 0; nt < 4; nt++) {
            int row = wm * 32 + mt * 16 + (lane >> 2);
            int col = wn * 32 + nt * 8 + (lane & 3) * 2;
            *(float2*)(sO + row * 66 + col) =
                make_float2(acc[mt][nt][0], acc[mt][nt][1]);
            *(float2*)(sO + (row + 8) * 66 + col) =
                make_float2(acc[mt][nt][2], acc[mt][nt][3]);
        }
    __syncthreads();

    if (EPI == 0 || (EPI == 1 && m0 < 512)) {
        for (int i = t; i < 8192; i += 256) {
            int n = i >> 7, m = i & 127;
            __nv_bfloat16 h, l; split2(sO[m * 66 + n], h, l);
            size_t o = ((size_t)b * NPIX + n0 + n) * 512 + m0 + m;
            Oth[o] = u16(h); Otl[o] = u16(l);
        }
    } else if (EPI == 1) {
        for (int i = t; i < 8192; i += 256) {
            int m = i >> 6, c = i & 63;
            __nv_bfloat16 h, l; split2(sO[m * 66 + c], h, l);
            size_t o = ((size_t)b * INNER + (m0 - 512 + m)) * NPIX + n0 + c;
            Ovh[o] = u16(h); Ovl[o] = u16(l);
        }
    } else {
        for (int i = t; i < 8192; i += 256) {
            int m = i >> 6, c = i & 63;
            Of[((size_t)b * M + m0 + m) * NPIX + n0 + c] = sO[m * 66 + c] + bias[m0 + m];
        }
    }
}

// ===========================================================================
// Flash attention, FA2-style: P and softmax fully register-resident.
// Each warp keeps per-slice (32-key) online stats and a partial O over all
// 64 d-cols; partials merged once in the epilogue (exact flash merge).
// 2 syncs/tile, K/V double-buffered cp.async.
// smem: Q 18432 | Kbuf0 18432 | Kbuf1 18432 | Vbuf0 18432 | Vbuf1 18432
// ===========================================================================
#define FA_SMEM 92160

#define FA_FILLQ() do {                                                        \
    _Pragma("unroll")                                                          \
    for (int r_ = 0; r_ < 4; r_++) {                                           \
        int c_ = t + r_ * 256;                                                 \
        int row_ = c_ >> 4, sub_ = c_ & 15, pl_ = sub_ >> 3, col_ = sub_ & 7;  \
        cp16(uQ + pl_ * 9216 + row_ * 144 + col_ * 16,                         \
             (pl_ ? qsl : qsh) + (size_t)row_ * INNER + col_ * 8);             \
    }                                                                          \
} while (0)
#define FA_FILLK(K0, BI) do {                                                  \
    _Pragma("unroll")                                                          \
    for (int r_ = 0; r_ < 4; r_++) {                                           \
        int c_ = t + r_ * 256;                                                 \
        int row_ = c_ >> 4, sub_ = c_ & 15, pl_ = sub_ >> 3, col_ = sub_ & 7;  \
        cp16(uK + (BI) * 18432 + pl_ * 9216 + row_ * 144 + col_ * 16,          \
             (pl_ ? ksl : ksh) + (size_t)((K0) + row_) * INNER + col_ * 8);    \
    }                                                                          \
} while (0)
#define FA_FILLV(K0, BI) do {                                                  \
    _Pragma("unroll")                                                          \
    for (int r_ = 0; r_ < 4; r_++) {                                           \
        int c_ = t + r_ * 256;                                                 \
        int row_ = c_ >> 4, sub_ = c_ & 15, pl_ = sub_ >> 3, col_ = sub_ & 7;  \
        cp16(uV + (BI) * 18432 + pl_ * 9216 + row_ * 144 + col_ * 16,          \
             (pl_ ? vsl : vsh) + (size_t)row_ * NPIX + (K0) + col_ * 8);       \
    }                                                                          \
} while (0)

__global__ __launch_bounds__(256)
void flash_attn_mma(const uint16_t* __restrict__ QTh, const uint16_t* __restrict__ QTl,
                    const uint16_t* __restrict__ KTh, const uint16_t* __restrict__ KTl,
                    const uint16_t* __restrict__ Vh,  const uint16_t* __restrict__ Vl,
                    uint16_t* __restrict__ AOTh, uint16_t* __restrict__ AOTl)
{
    extern __shared__ char smc[];
    const uint32_t base = smem_u32(smc);
    const uint32_t uQ = base;                 // hi, lo at +9216
    const uint32_t uK = base + 18432;         // buf BI at +BI*18432, lo +9216
    const uint32_t uV = base + 55296;
    // epilogue-only views (overlay the K-buffer region, dead after the loop)
    float* sS = (float*)(smc + 18432);        // [64][68]
    float* sL = (float*)(smc + 18432 + 17408);
    float* em = (float*)(smc + 18432 + 17664);  // [2][64]
    float* el = (float*)(smc + 18432 + 18176);  // [2][64]

    const int t    = threadIdx.x;
    const int warp = t >> 5, lane = t & 31;
    const int wm   = warp & 3, wn = warp >> 2;
    const int q0   = blockIdx.x * 64;
    const int bh   = blockIdx.y;
    const int b    = bh >> 3, h = bh & 7;

    const uint16_t* qsh = QTh + ((size_t)b * NPIX + q0) * INNER + h * 64;
    const uint16_t* qsl = QTl + ((size_t)b * NPIX + q0) * INNER + h * 64;
    const uint16_t* ksh = KTh + (size_t)b * NPIX * INNER + h * 64;
    const uint16_t* ksl = KTl + (size_t)b * NPIX * INNER + h * 64;
    const uint16_t* vsh = Vh + ((size_t)b * INNER + h * 64) * NPIX;
    const uint16_t* vsl = Vl + ((size_t)b * INNER + h * 64) * NPIX;

    const int arow  = lane & 15;
    const int acolb = (lane >> 4) * 16;
    const int brow  = (lane & 7) + ((lane >> 4) << 3);
    const int bcolb = ((lane >> 3) & 1) * 16;

    FA_FILLQ(); FA_FILLK(0, 0); FA_FILLV(0, 0); CP_COMMIT();
    FA_FILLK(64, 1); FA_FILLV(64, 1); CP_COMMIT();

    float accO[8][4] = {};                    // partial O: rows wm*16.., d=0..63
    float m0 = -1e30f, m1 = -1e30f, l0 = 0.f, l1 = 0.f;

    for (int kt = 0; kt < 16; kt++) {
        if (kt < 15) { CP_WAIT1(); } else { CP_WAIT0(); }
        __syncthreads();
        const uint32_t uKb = uK + (kt & 1) * 18432;
        const uint32_t uVb = uV + (kt & 1) * 18432;

        // S = Qs · K^T   (warp's 32-key slice: cols wn*32..+32)
        float s[4][4] = {};
        #pragma unroll
        for (int ks = 0; ks < 4; ks++) {
            const int kbyte = ks * 32;
            uint32_t ah[4], al[4], bhv[2][4], blv[2][4];
            {
                uint32_t off = (uint32_t)((wm * 16 + arow) * ASTR) * 2 + kbyte + acolb;
                ldmx4(ah, uQ + off);
                ldmx4(al, uQ + 9216 + off);
            }
            #pragma unroll
            for (int nt2 = 0; nt2 < 2; nt2++) {
                uint32_t off = (uint32_t)((wn * 32 + nt2 * 16 + brow) * ASTR) * 2
                             + kbyte + bcolb;
                ldmx4(bhv[nt2], uKb + off);
                ldmx4(blv[nt2], uKb + 9216 + off);
            }
            #pragma unroll
            for (int nt = 0; nt < 4; nt++) {
                uint32_t b0h = bhv[nt >> 1][(nt & 1) * 2];
                uint32_t b1h = bhv[nt >> 1][(nt & 1) * 2 + 1];
                uint32_t b0l = blv[nt >> 1][(nt & 1) * 2];
                uint32_t b1l = blv[nt >> 1][(nt & 1) * 2 + 1];
                mma_bf16(s[nt], ah, b0h, b1h);
                mma_bf16(s[nt], ah, b0l, b1l);
                mma_bf16(s[nt], al, b0h, b1h);
            }
        }

        // In-register online softmax over this warp's 32-key slice
        float tm0 = -1e30f, tm1 = -1e30f;
        #pragma unroll
        for (int nt = 0; nt < 4; nt++) {
            tm0 = fmaxf(tm0, fmaxf(s[nt][0], s[nt][1]));
            tm1 = fmaxf(tm1, fmaxf(s[nt][2], s[nt][3]));
        }
        tm0 = fmaxf(tm0, __shfl_xor_sync(0xffffffffu, tm0, 1));
        tm0 = fmaxf(tm0, __shfl_xor_sync(0xffffffffu, tm0, 2));
        tm1 = fmaxf(tm1, __shfl_xor_sync(0xffffffffu, tm1, 1));
        tm1 = fmaxf(tm1, __shfl_xor_sync(0xffffffffu, tm1, 2));
        float mn0 = fmaxf(m0, tm0), mn1 = fmaxf(m1, tm1);
        float f0 = __expf(m0 - mn0), f1 = __expf(m1 - mn1);
        float sum0 = 0.f, sum1 = 0.f;
        #pragma unroll
        for (int nt = 0; nt < 4; nt++) {
            s[nt][0] = __expf(s[nt][0] - mn0);
            s[nt][1] = __expf(s[nt][1] - mn0);
            s[nt][2] = __expf(s[nt][2] - mn1);
            s[nt][3] = __expf(s[nt][3] - mn1);
            sum0 += s[nt][0] + s[nt][1];
            sum1 += s[nt][2] + s[nt][3];
        }
        sum0 += __shfl_xor_sync(0xffffffffu, sum0, 1);
        sum0 += __shfl_xor_sync(0xffffffffu, sum0, 2);
        sum1 += __shfl_xor_sync(0xffffffffu, sum1, 1);
        sum1 += __shfl_xor_sync(0xffffffffu, sum1, 2);
        l0 = l0 * f0 + sum0; l1 = l1 * f1 + sum1;
        m0 = mn0; m1 = mn1;
        #pragma unroll
        for (int nt = 0; nt < 8; nt++) {
            accO[nt][0] *= f0; accO[nt][1] *= f0;
            accO[nt][2] *= f1; accO[nt][3] *= f1;
        }

        // P fragments in registers (C-frag layout == A-frag layout), hi/lo
        uint32_t pfh[2][4], pfl[2][4];
        #pragma unroll
        for (int kc = 0; kc < 2; kc++) {
            packsplit2(s[2 * kc][0],     s[2 * kc][1],     pfh[kc][0], pfl[kc][0]);
            packsplit2(s[2 * kc][2],     s[2 * kc][3],     pfh[kc][1], pfl[kc][1]);
            packsplit2(s[2 * kc + 1][0], s[2 * kc + 1][1], pfh[kc][2], pfl[kc][2]);
            packsplit2(s[2 * kc + 1][2], s[2 * kc + 1][3], pfh[kc][3], pfl[kc][3]);
        }

        // O_partial += P · V over this warp's keys, all 64 d-cols
        #pragma unroll
        for (int kc = 0; kc < 2; kc++) {
            const int kbyte = wn * 64 + kc * 32;
            uint32_t bhv[4][4], blv[4][4];
            #pragma unroll
            for (int nt2 = 0; nt2 < 4; nt2++) {
                uint32_t off = (uint32_t)((nt2 * 16 + brow) * ASTR) * 2 + kbyte + bcolb;
                ldmx4(bhv[nt2], uVb + off);
                ldmx4(blv[nt2], uVb + 9216 + off);
            }
            #pragma unroll
            for (int nt = 0; nt < 8; nt++) {
                uint32_t b0h = bhv[nt >> 1][(nt & 1) * 2];
                uint32_t b1h = bhv[nt >> 1][(nt & 1) * 2 + 1];
                uint32_t b0l = blv[nt >> 1][(nt & 1) * 2];
                uint32_t b1l = blv[nt >> 1][(nt & 1) * 2 + 1];
                mma_bf16(accO[nt], pfh[kc], b0h, b1h);
                mma_bf16(accO[nt], pfh[kc], b0l, b1l);
                mma_bf16(accO[nt], pfl[kc], b0h, b1h);
            }
        }
        __syncthreads();
        if (kt < 14) {
            FA_FILLK((kt + 2) * 64, kt & 1);
            FA_FILLV((kt + 2) * 64, kt & 1);
            CP_COMMIT();
        }
    }

    // Epilogue: merge the two per-warp partials (exact flash merge), GELU, out
    {
        int r0 = wm * 16 + (lane >> 2);
        if ((lane & 3) == 0) {
            em[wn * 64 + r0] = m0;     el[wn * 64 + r0] = l0;
            em[wn * 64 + r0 + 8] = m1; el[wn * 64 + r0 + 8] = l1;
        }
    }
    __syncthreads();
    {
        int r0 = wm * 16 + (lane >> 2);
        float mo0 = em[(wn ^ 1) * 64 + r0],     lo0 = el[(wn ^ 1) * 64 + r0];
        float mo1 = em[(wn ^ 1) * 64 + r0 + 8], lo1 = el[(wn ^ 1) * 64 + r0 + 8];
        float M0 = fmaxf(m0, mo0), M1 = fmaxf(m1, mo1);
        float myf0 = __expf(m0 - M0), myf1 = __expf(m1 - M1);
        float L0 = l0 * myf0 + lo0 * __expf(mo0 - M0);
        float L1 = l1 * myf1 + lo1 * __expf(mo1 - M1);
        if (wn == 0) {
            #pragma unroll
            for (int nt = 0; nt < 8; nt++) {
                int col = nt * 8 + (lane & 3) * 2;
                *(float2*)(sS + r0 * 68 + col) =
                    make_float2(accO[nt][0] * myf0, accO[nt][1] * myf0);
                *(float2*)(sS + (r0 + 8) * 68 + col) =
                    make_float2(accO[nt][2] * myf1, accO[nt][3] * myf1);
            }
            if ((lane & 3) == 0) { sL[r0] = L0; sL[r0 + 8] = L1; }
        }
        __syncthreads();
        if (wn == 1) {
            #pragma unroll
            for (int nt = 0; nt < 8; nt++) {
                int col = nt * 8 + (lane & 3) * 2;
                float2 v0 = *(float2*)(sS + r0 * 68 + col);
                float2 v1 = *(float2*)(sS + (r0 + 8) * 68 + col);
                v0.x += accO[nt][0] * myf0; v0.y += accO[nt][1] * myf0;
                v1.x += accO[nt][2] * myf1; v1.y += accO[nt][3] * myf1;
                *(float2*)(sS + r0 * 68 + col) = v0;
                *(float2*)(sS + (r0 + 8) * 68 + col) = v1;
            }
        }
    }
    __syncthreads();
    {
        uint16_t* aoh = AOTh + ((size_t)b * NPIX + q0) * INNER + h * 64;
        uint16_t* aol = AOTl + ((size_t)b * NPIX + q0) * INNER + h * 64;
        for (int idx = t; idx < 4096; idx += 256) {
            int q = idx >> 6, d = idx & 63;
            float v = sS[q * 68 + d] / sL[q];
            float g = 0.5f * v * (1.f + erff(v * 0.70710678118654752f));
            __nv_bfloat16 hh, ll; split2(g, hh, ll);
            size_t o = (size_t)q * INNER + d;
            aoh[o] = u16(hh); aol[o] = u16(ll);
        }
    }
}

// ---------------------------------------------------------------------------
extern "C" void kernel_launch(void* const* d_in, const int* in_sizes, int n_in,
                              void* d_out, int out_size)
{
    const float* x    = (const float*)d_in[0];
    const float* Wq   = (const float*)d_in[1];
    const float* Wkv  = (const float*)d_in[2];
    const float* Wout = (const float*)d_in[3];
    const float* bout = (const float*)d_in[4];
    float* out = (float*)d_out;

    uint16_t *wqh, *wql, *wkvh, *wkvl, *woh, *wol;
    uint16_t *xth, *xtl, *qth, *qtl, *kth, *ktl, *vh, *vl, *aoh, *aol;
    cudaGetSymbolAddress((void**)&wqh,  g_Wq_h);  cudaGetSymbolAddress((void**)&wql,  g_Wq_l);
    cudaGetSymbolAddress((void**)&wkvh, g_Wkv_h); cudaGetSymbolAddress((void**)&wkvl, g_Wkv_l);
    cudaGetSymbolAddress((void**)&woh,  g_Wo_h);  cudaGetSymbolAddress((void**)&wol,  g_Wo_l);
    cudaGetSymbolAddress((void**)&xth,  g_XT_h);  cudaGetSymbolAddress((void**)&xtl,  g_XT_l);
    cudaGetSymbolAddress((void**)&qth,  g_QT_h);  cudaGetSymbolAddress((void**)&qtl,  g_QT_l);
    cudaGetSymbolAddress((void**)&kth,  g_KT_h);  cudaGetSymbolAddress((void**)&ktl,  g_KT_l);
    cudaGetSymbolAddress((void**)&vh,   g_V_h);   cudaGetSymbolAddress((void**)&vl,   g_V_l);
    cudaGetSymbolAddress((void**)&aoh,  g_AOT_h); cudaGetSymbolAddress((void**)&aol,  g_AOT_l);

    dim3 blk(256);

    // 0) weight planes (Wq scale-folded; Wkv tap-major permuted) + XT
    split_planes<<<(INNER * C_IN + 255) / 256, blk>>>(Wq, wqh, wql, INNER * C_IN, 0.125f);
    split_wkv_perm<<<(MKV * KCONV + 255) / 256, blk>>>(Wkv, wkvh, wkvl);
    split_planes<<<(C_IN * INNER + 255) / 256, blk>>>(Wout, woh, wol, C_IN * INNER, 1.f);
    transXT<<<dim3(32, 8, BATCH), blk>>>(x, xth, xtl);

    // 1) Q^T = (Wq/8 · x)^T  (K=256, 4 panels)
    cudaFuncSetAttribute(gemm_planes<0,0>, cudaFuncAttributeMaxDynamicSharedMemorySize, GP_SMEM);
    gemm_planes<0,0><<<dim3(16, 4, BATCH), blk, GP_SMEM>>>(
        wqh, wql, xth, xtl, C_IN, 4, qth, qtl, nullptr, nullptr, nullptr, nullptr, INNER);

    // 2) KV = conv3x3 as 9 shifted 1x1 GEMMs on XT (36 panels)
    cudaFuncSetAttribute(gemm_planes<1,1>, cudaFuncAttributeMaxDynamicSharedMemorySize, GP_SMEM);
    gemm_planes<1,1><<<dim3(16, 8, BATCH), blk, GP_SMEM>>>(
        wkvh, wkvl, xth, xtl, KCONV, 36, kth, ktl, vh, vl, nullptr, nullptr, MKV);

    // 3) attention + GELU -> AOT planes (register-resident FA2)
    cudaFuncSetAttribute(flash_attn_mma, cudaFuncAttributeMaxDynamicSharedMemorySize, FA_SMEM);
    flash_attn_mma<<<dim3(16, BATCH * HEADS), blk, FA_SMEM>>>(
        qth, qtl, kth, ktl, vh, vl, aoh, aol);

    // 4) out = Wout · gelu_attn + bout  (K=512, 8 panels)
    cudaFuncSetAttribute(gemm_planes<2,0>, cudaFuncAttributeMaxDynamicSharedMemorySize, GP_SMEM);
    gemm_planes<2,0><<<dim3(16, 2, BATCH), blk, GP_SMEM>>>(
        woh, wol, aoh, aol, INNER, 8, nullptr, nullptr, nullptr, nullptr, out, bout, 256);
}

// round 16
// speedup vs baseline: 1.2876x; 1.0147x over previous
#include <cuda_runtime.h>
#include <cuda_bf16.h>
#include <cstdint>
#include <math.h>

// Problem constants
#define BATCH  8
#define C_IN   256
#define NPIX   1024   // 32*32
#define INNER  512
#define HEADS  8
#define DH     64
#define KCONV  2304   // 256*9
#define MKV    1024

// ---------------------------------------------------------------------------
// bf16 hi/lo PLANE format: v ~ hi + lo. Wkv stored PERMUTED k' = tap*256+ci
// so the conv runs as 9 shifted 1x1 GEMMs on XT via a per-CTA halo slab.
// ---------------------------------------------------------------------------
__device__ uint16_t g_Wq_h [(size_t)INNER * C_IN],  g_Wq_l [(size_t)INNER * C_IN];
__device__ uint16_t g_Wkv_h[(size_t)MKV * KCONV],   g_Wkv_l[(size_t)MKV * KCONV];
__device__ uint16_t g_Wo_h [(size_t)C_IN * INNER],  g_Wo_l [(size_t)C_IN * INNER];
__device__ uint16_t g_XT_h [(size_t)BATCH * NPIX * C_IN];
__device__ uint16_t g_XT_l [(size_t)BATCH * NPIX * C_IN];
__device__ uint16_t g_QT_h [(size_t)BATCH * NPIX * INNER];
__device__ uint16_t g_QT_l [(size_t)BATCH * NPIX * INNER];
__device__ uint16_t g_KT_h [(size_t)BATCH * NPIX * INNER];
__device__ uint16_t g_KT_l [(size_t)BATCH * NPIX * INNER];
__device__ uint16_t g_V_h  [(size_t)BATCH * INNER * NPIX];
__device__ uint16_t g_V_l  [(size_t)BATCH * INNER * NPIX];
__device__ uint16_t g_AOT_h[(size_t)BATCH * NPIX * INNER];
__device__ uint16_t g_AOT_l[(size_t)BATCH * NPIX * INNER];

__device__ __forceinline__ void split2(float v, __nv_bfloat16& h, __nv_bfloat16& l) {
    h = __float2bfloat16(v);
    l = __float2bfloat16(v - __bfloat162float(h));
}
__device__ __forceinline__ uint16_t u16(__nv_bfloat16 x) { return __bfloat16_as_ushort(x); }
__device__ __forceinline__ void packsplit2(float a, float b, uint32_t& h, uint32_t& l) {
    __nv_bfloat16 ah, al, bh, bl;
    split2(a, ah, al); split2(b, bh, bl);
    h = (uint32_t)u16(ah) | ((uint32_t)u16(bh) << 16);
    l = (uint32_t)u16(al) | ((uint32_t)u16(bl) << 16);
}

// ===========================================================================
// mma.sync / ldmatrix / cp.async helpers (plain sm_103 — tcgen05 is 'a'-only)
// ===========================================================================
__device__ __forceinline__ uint32_t smem_u32(const void* p) {
    uint32_t a;
    asm("{ .reg .u64 t; cvta.to.shared.u64 t, %1; cvt.u32.u64 %0, t; }"
        : "=r"(a) : "l"(p));
    return a;
}
__device__ __forceinline__ void ldmx4(uint32_t* r, uint32_t addr) {
    asm volatile("ldmatrix.sync.aligned.m8n8.x4.shared.b16 {%0,%1,%2,%3}, [%4];"
        : "=r"(r[0]), "=r"(r[1]), "=r"(r[2]), "=r"(r[3]) : "r"(addr));
}
__device__ __forceinline__ void mma_bf16(float* c, const uint32_t* a,
                                         uint32_t b0, uint32_t b1) {
    asm volatile(
        "mma.sync.aligned.m16n8k16.row.col.f32.bf16.bf16.f32 "
        "{%0,%1,%2,%3}, {%4,%5,%6,%7}, {%8,%9}, {%0,%1,%2,%3};"
        : "+f"(c[0]), "+f"(c[1]), "+f"(c[2]), "+f"(c[3])
        : "r"(a[0]), "r"(a[1]), "r"(a[2]), "r"(a[3]), "r"(b0), "r"(b1));
}
__device__ __forceinline__ void cp16(uint32_t dst, const void* src) {
    asm volatile("cp.async.cg.shared.global [%0], [%1], 16;" :: "r"(dst), "l"(src));
}
__device__ __forceinline__ void cp16z(uint32_t dst, const void* src, uint32_t bytes) {
    asm volatile("cp.async.cg.shared.global [%0], [%1], 16, %2;"
        :: "r"(dst), "l"(src), "r"(bytes));
}
#define CP_COMMIT() asm volatile("cp.async.commit_group;")
#define CP_WAIT1()  asm volatile("cp.async.wait_group 1;")
#define CP_WAIT0()  asm volatile("cp.async.wait_group 0;")

#define ASTR 72   // smem row stride in halfwords (144B): conflict-free ldmatrix

// ===========================================================================
// prep kernels
// ===========================================================================
__global__ __launch_bounds__(256)
void split_planes(const float* __restrict__ in, uint16_t* __restrict__ oh,
                  uint16_t* __restrict__ ol, int n, float scale)
{
    int i = blockIdx.x * 256 + threadIdx.x;
    if (i < n) {
        float v = in[i] * scale;
        __nv_bfloat16 h, l; split2(v, h, l);
        oh[i] = u16(h); ol[i] = u16(l);
    }
}

__global__ __launch_bounds__(256)
void split_wkv_perm(const float* __restrict__ in, uint16_t* __restrict__ oh,
                    uint16_t* __restrict__ ol)
{
    int i = blockIdx.x * 256 + threadIdx.x;
    if (i < MKV * KCONV) {
        int co = i / KCONV, r = i - co * KCONV;   // r = tap*256 + ci
        int tap = r >> 8, ci = r & 255;
        float v = in[(size_t)co * KCONV + ci * 9 + tap];
        __nv_bfloat16 h, l; split2(v, h, l);
        oh[i] = u16(h); ol[i] = u16(l);
    }
}

__global__ __launch_bounds__(256)
void transXT(const float* __restrict__ x, uint16_t* __restrict__ XTh,
             uint16_t* __restrict__ XTl)
{
    __shared__ float tile[32][33];
    int tx = threadIdx.x & 31, ty = threadIdx.x >> 5;
    int p0 = blockIdx.x * 32, c0 = blockIdx.y * 32, b = blockIdx.z;
    const float* xb = x + (size_t)b * C_IN * NPIX;
    #pragma unroll
    for (int r = 0; r < 4; r++)
        tile[ty * 4 + r][tx] = xb[(size_t)(c0 + ty * 4 + r) * NPIX + p0 + tx];
    __syncthreads();
    #pragma unroll
    for (int r = 0; r < 4; r++) {
        int pix = p0 + ty * 4 + r;
        float v = tile[tx][ty * 4 + r];
        __nv_bfloat16 h, l; split2(v, h, l);
        size_t o = ((size_t)b * NPIX + pix) * C_IN + c0 + tx;
        XTh[o] = u16(h); XTl[o] = u16(l);
    }
}

// ===========================================================================
// conv_q: fused 3x3-conv (as 9 slab-shifted 1x1 GEMMs) + Q projection.
// blockIdx.y < 8 : conv rows (KV), K=2304 = 4 cig x 9 taps
// blockIdx.y >= 8: Q rows,        K=256  = 4 cig x 1 tap (center)
// Per CTA: 64 pixels (2 image rows). Halo slab: 4 prows x 34 pcols x 64 ci,
// zero-padded; all taps read from it via per-lane ldmatrix row addresses.
// smem: slab (2 planes x 19584) + A double-buf (2 x 36864) = 112896 B -> 2 CTA/SM
// ===========================================================================
#define CV_SLAB_PL 19584
#define CV_SLAB    (2 * CV_SLAB_PL)            // 39168
#define CV_ABUF    36864
#define CV_SMEM    (CV_SLAB + 2 * CV_ABUF)     // 112896

__device__ __forceinline__ void cv_fillA(uint32_t ua, int t,
    const uint16_t* __restrict__ Ah, const uint16_t* __restrict__ Al,
    int m0, int Krow, int k0)
{
    #pragma unroll
    for (int r = 0; r < 8; r++) {
        int c = t + r * 256;
        int row = c >> 4, sub = c & 15, pl = sub >> 3, col = sub & 7;
        cp16(ua + pl * 18432 + row * 144 + col * 16,
             (pl ? Al : Ah) + (size_t)(m0 + row) * Krow + k0 + col * 8);
    }
}

__device__ __forceinline__ void cv_fillSlab(uint32_t us, int t,
    const uint16_t* __restrict__ Bh, const uint16_t* __restrict__ Bl,
    int py0, int cig)
{
    for (int i = t; i < 2176; i += 256) {
        int pl = (i >= 1088) ? 1 : 0;
        int j  = pl ? i - 1088 : i;
        int cell = j >> 3, col = j & 7;
        int prow = cell / 34, pcol = cell - prow * 34;
        int y = py0 - 1 + prow, px = pcol - 1;
        bool ok = ((unsigned)y < 32u) && ((unsigned)px < 32u);
        size_t sp = (size_t)(ok ? (y * 32 + px) : 0) * C_IN + cig * 64 + col * 8;
        cp16z(us + pl * CV_SLAB_PL + cell * 144 + col * 16,
              (pl ? Bl : Bh) + sp, ok ? 16u : 0u);
    }
}

__global__ __launch_bounds__(256)
void conv_q(const uint16_t* __restrict__ Wkvh, const uint16_t* __restrict__ Wkvl,
            const uint16_t* __restrict__ Wqh,  const uint16_t* __restrict__ Wql,
            const uint16_t* __restrict__ XTh,  const uint16_t* __restrict__ XTl,
            uint16_t* __restrict__ Kth, uint16_t* __restrict__ Ktl,
            uint16_t* __restrict__ Vvh, uint16_t* __restrict__ Vvl,
            uint16_t* __restrict__ Qth, uint16_t* __restrict__ Qtl)
{
    extern __shared__ char smem[];
    const uint32_t us = smem_u32(smem);        // slab
    const uint32_t ua = us + CV_SLAB;          // A buffers
    const int t = threadIdx.x;
    const int warp = t >> 5, lane = t & 31;
    const int wm = warp & 3, wn = warp >> 2;
    const int n0 = blockIdx.x * 64, by = blockIdx.y, b = blockIdx.z;
    const bool qm = (by >= 8);
    const int m0 = qm ? (by - 8) * 128 : by * 128;
    const int Krow = qm ? C_IN : KCONV;
    const uint16_t* Ah = qm ? Wqh : Wkvh;
    const uint16_t* Al = qm ? Wql : Wkvl;
    const uint16_t* Bh = XTh + (size_t)b * NPIX * C_IN;
    const uint16_t* Bl = XTl + (size_t)b * NPIX * C_IN;
    const int py0 = n0 >> 5;
    const int NT = qm ? 1 : 9;

    const int arow  = lane & 15;
    const int acolb = (lane >> 4) * 16;
    const int brow  = (lane & 7) + ((lane >> 4) << 3);
    const int bcolb = ((lane >> 3) & 1) * 16;
    int pyl[2], pxl[2];
    #pragma unroll
    for (int nt2 = 0; nt2 < 2; nt2++) {
        int pix = wn * 32 + nt2 * 16 + brow;
        pyl[nt2] = pix >> 5; pxl[nt2] = pix & 31;
    }

    float acc[2][4][4] = {};

    cv_fillSlab(us, t, Bh, Bl, py0, 0);
    cv_fillA(ua, t, Ah, Al, m0, Krow, 0);
    CP_COMMIT();

    for (int cig = 0; cig < 4; cig++) {
        for (int tp = 0; tp < NT; tp++) {
            const int idx = cig * NT + tp;
            const int buf = idx & 1;
            // prefetch next A panel
            int ncig = cig, ntp = tp + 1;
            if (ntp == NT) { ncig = cig + 1; ntp = 0; }
            if (ncig < 4) {
                int nk0 = qm ? ncig * 64 : (ntp * 256 + ncig * 64);
                cv_fillA(ua + (buf ^ 1) * CV_ABUF, t, Ah, Al, m0, Krow, nk0);
                CP_COMMIT(); CP_WAIT1();
            } else { CP_WAIT0(); }
            __syncthreads();

            const int dy = qm ? 0 : (tp / 3 - 1);
            const int dx = qm ? 0 : (tp - (tp / 3) * 3 - 1);
            const uint32_t uA = ua + buf * CV_ABUF;
            uint32_t bbase[2];
            #pragma unroll
            for (int nt2 = 0; nt2 < 2; nt2++) {
                int srow = (pyl[nt2] + 1 + dy) * 34 + (pxl[nt2] + 1 + dx);
                bbase[nt2] = us + (uint32_t)srow * 144 + bcolb;
            }
            #pragma unroll
            for (int ks = 0; ks < 4; ks++) {
                const int kb = ks * 32;
                uint32_t ah[2][4], al[2][4], bh[2][4], bl[2][4];
                #pragma unroll
                for (int mt = 0; mt < 2; mt++) {
                    uint32_t off = (uint32_t)((wm * 32 + mt * 16 + arow) * ASTR) * 2
                                 + kb + acolb;
                    ldmx4(ah[mt], uA + off);
                    ldmx4(al[mt], uA + 18432 + off);
                }
                #pragma unroll
                for (int nt2 = 0; nt2 < 2; nt2++) {
                    ldmx4(bh[nt2], bbase[nt2] + kb);
                    ldmx4(bl[nt2], bbase[nt2] + CV_SLAB_PL + kb);
                }
                #pragma unroll
                for (int mt = 0; mt < 2; mt++)
                    #pragma unroll
                    for (int nt = 0; nt < 4; nt++) {
                        uint32_t b0h = bh[nt >> 1][(nt & 1) * 2];
                        uint32_t b1h = bh[nt >> 1][(nt & 1) * 2 + 1];
                        uint32_t b0l = bl[nt >> 1][(nt & 1) * 2];
                        uint32_t b1l = bl[nt >> 1][(nt & 1) * 2 + 1];
                        mma_bf16(acc[mt][nt], ah[mt], b0h, b1h);
                        mma_bf16(acc[mt][nt], ah[mt], b0l, b1l);
                        mma_bf16(acc[mt][nt], al[mt], b0h, b1h);
                    }
            }
            __syncthreads();
            // slab refill for next cig (after all taps of this cig consumed it)
            if (tp == NT - 1 && cig < 3) {
                cv_fillSlab(us, t, Bh, Bl, py0, cig + 1);
                CP_COMMIT();
            }
        }
    }

    // epilogue: stage fp32, write planes
    float* sO = (float*)smem;   // [128][66]
    #pragma unroll
    for (int mt = 0; mt < 2; mt++)
        #pragma unroll
        for (int nt = 0; nt < 4; nt++) {
            int row = wm * 32 + mt * 16 + (lane >> 2);
            int col = wn * 32 + nt * 8 + (lane & 3) * 2;
            *(float2*)(sO + row * 66 + col) =
                make_float2(acc[mt][nt][0], acc[mt][nt][1]);
            *(float2*)(sO + (row + 8) * 66 + col) =
                make_float2(acc[mt][nt][2], acc[mt][nt][3]);
        }
    __syncthreads();

    if (qm) {
        for (int i = t; i < 8192; i += 256) {
            int n = i >> 7, m = i & 127;
            __nv_bfloat16 h, l; split2(sO[m * 66 + n], h, l);
            size_t o = ((size_t)b * NPIX + n0 + n) * 512 + m0 + m;
            Qth[o] = u16(h); Qtl[o] = u16(l);
        }
    } else if (m0 < 512) {
        for (int i = t; i < 8192; i += 256) {
            int n = i >> 7, m = i & 127;
            __nv_bfloat16 h, l; split2(sO[m * 66 + n], h, l);
            size_t o = ((size_t)b * NPIX + n0 + n) * 512 + m0 + m;
            Kth[o] = u16(h); Ktl[o] = u16(l);
        }
    } else {
        for (int i = t; i < 8192; i += 256) {
            int m = i >> 6, c = i & 63;
            __nv_bfloat16 h, l; split2(sO[m * 66 + c], h, l);
            size_t o = ((size_t)b * INNER + (m0 - 512 + m)) * NPIX + n0 + c;
            Vvh[o] = u16(h); Vvl[o] = u16(l);
        }
    }
}

// ===========================================================================
// Plane GEMM (TAPS=0 path only; used for the output projection), unchanged.
// ===========================================================================
#define GP_BUF  55296
#define GP_SMEM (2 * GP_BUF)

__device__ __forceinline__ void gp_fill(
    uint32_t ub, int t, int panel, int m0, int n0, int K,
    const uint16_t* __restrict__ Ah, const uint16_t* __restrict__ Al,
    const uint16_t* __restrict__ Bh, const uint16_t* __restrict__ Bl)
{
    const int k0 = panel * 64;
    #pragma unroll
    for (int r = 0; r < 8; r++) {
        int c = t + r * 256;
        int row = c >> 4, sub = c & 15, pl = sub >> 3, col = sub & 7;
        cp16(ub + pl * 18432 + row * 144 + col * 16,
             (pl ? Al : Ah) + (size_t)(m0 + row) * K + k0 + col * 8);
    }
    #pragma unroll
    for (int r = 0; r < 4; r++) {
        int c = t + r * 256;
        int row = c >> 4, sub = c & 15, pl = sub >> 3, col = sub & 7;
        cp16(ub + 36864 + pl * 9216 + row * 144 + col * 16,
             (pl ? Bl : Bh) + (size_t)(n0 + row) * K + k0 + col * 8);
    }
}

__global__ __launch_bounds__(256)
void gemm_out(const uint16_t* __restrict__ Ah, const uint16_t* __restrict__ Al,
              const uint16_t* __restrict__ Bh, const uint16_t* __restrict__ Bl,
              int K, int NP, float* __restrict__ Of,
              const float* __restrict__ bias, int M)
{
    extern __shared__ char smem[];
    const uint32_t us = smem_u32(smem);
    const int t = threadIdx.x;
    const int warp = t >> 5, lane = t & 31;
    const int wm = warp & 3, wn = warp >> 2;
    const int n0 = blockIdx.x * 64, m0 = blockIdx.y * 128;
    const int b  = blockIdx.z;
    const uint16_t* Bhb = Bh + (size_t)b * NPIX * K;
    const uint16_t* Blb = Bl + (size_t)b * NPIX * K;

    const int arow  = lane & 15;
    const int acolb = (lane >> 4) * 16;
    const int brow  = (lane & 7) + ((lane >> 4) << 3);
    const int bcolb = ((lane >> 3) & 1) * 16;

    float acc[2][4][4] = {};

    gp_fill(us, t, 0, m0, n0, K, Ah, Al, Bhb, Blb);
    CP_COMMIT();
    for (int p = 0; p < NP; p++) {
        if (p + 1 < NP) {
            gp_fill(us + ((p + 1) & 1) * GP_BUF, t, p + 1, m0, n0, K,
                    Ah, Al, Bhb, Blb);
            CP_COMMIT(); CP_WAIT1();
        } else { CP_WAIT0(); }
        __syncthreads();
        uint32_t ub  = us + (p & 1) * GP_BUF;
        uint32_t uAh = ub, uAl = ub + 18432, uBh = ub + 36864, uBl = ub + 46080;
        #pragma unroll
        for (int ks = 0; ks < 4; ks++) {
            const int kb = ks * 32;
            uint32_t ah[2][4], al[2][4], bh[2][4], bl[2][4];
            #pragma unroll
            for (int mt = 0; mt < 2; mt++) {
                uint32_t off = (uint32_t)((wm * 32 + mt * 16 + arow) * ASTR) * 2
                             + kb + acolb;
                ldmx4(ah[mt], uAh + off);
                ldmx4(al[mt], uAl + off);
            }
            #pragma unroll
            for (int nt2 = 0; nt2 < 2; nt2++) {
                uint32_t off = (uint32_t)((wn * 32 + nt2 * 16 + brow) * ASTR) * 2
                             + kb + bcolb;
                ldmx4(bh[nt2], uBh + off);
                ldmx4(bl[nt2], uBl + off);
            }
            #pragma unroll
            for (int mt = 0; mt < 2; mt++)
                #pragma unroll
                for (int nt = 0; nt < 4; nt++) {
                    uint32_t b0h = bh[nt >> 1][(nt & 1) * 2];
                    uint32_t b1h = bh[nt >> 1][(nt & 1) * 2 + 1];
                    uint32_t b0l = bl[nt >> 1][(nt & 1) * 2];
                    uint32_t b1l = bl[nt >> 1][(nt & 1) * 2 + 1];
                    mma_bf16(acc[mt][nt], ah[mt], b0h, b1h);
                    mma_bf16(acc[mt][nt], ah[mt], b0l, b1l);
                    mma_bf16(acc[mt][nt], al[mt], b0h, b1h);
                }
        }
        __syncthreads();
    }

    float* sO = (float*)smem;   // [128][66]
    #pragma unroll
    for (int mt = 0; mt < 2; mt++)
        #pragma unroll
        for (int nt = 0; nt < 4; nt++) {
            int row = wm * 32 + mt * 16 + (lane >> 2);
            int col = wn * 32 + nt * 8 + (lane & 3) * 2;
            *(float2*)(sO + row * 66 + col) =
                make_float2(acc[mt][nt][0], acc[mt][nt][1]);
            *(float2*)(sO + (row + 8) * 66 + col) =
                make_float2(acc[mt][nt][2], acc[mt][nt][3]);
        }
    __syncthreads();
    for (int i = t; i < 8192; i += 256) {
        int m = i >> 6, c = i & 63;
        Of[((size_t)b * M + m0 + m) * NPIX + n0 + c] = sO[m * 66 + c] + bias[m0 + m];
    }
}

// ===========================================================================
// Flash attention (unchanged from R15, validated): register-resident FA2.
// ===========================================================================
#define FA_SMEM 92160

#define FA_FILLQ() do {                                                        \
    _Pragma("unroll")                                                          \
    for (int r_ = 0; r_ < 4; r_++) {                                           \
        int c_ = t + r_ * 256;                                                 \
        int row_ = c_ >> 4, sub_ = c_ & 15, pl_ = sub_ >> 3, col_ = sub_ & 7;  \
        cp16(uQ + pl_ * 9216 + row_ * 144 + col_ * 16,                         \
             (pl_ ? qsl : qsh) + (size_t)row_ * INNER + col_ * 8);             \
    }                                                                          \
} while (0)
#define FA_FILLK(K0, BI) do {                                                  \
    _Pragma("unroll")                                                          \
    for (int r_ = 0; r_ < 4; r_++) {                                           \
        int c_ = t + r_ * 256;                                                 \
        int row_ = c_ >> 4, sub_ = c_ & 15, pl_ = sub_ >> 3, col_ = sub_ & 7;  \
        cp16(uK + (BI) * 18432 + pl_ * 9216 + row_ * 144 + col_ * 16,          \
             (pl_ ? ksl : ksh) + (size_t)((K0) + row_) * INNER + col_ * 8);    \
    }                                                                          \
} while (0)
#define FA_FILLV(K0, BI) do {                                                  \
    _Pragma("unroll")                                                          \
    for (int r_ = 0; r_ < 4; r_++) {                                           \
        int c_ = t + r_ * 256;                                                 \
        int row_ = c_ >> 4, sub_ = c_ & 15, pl_ = sub_ >> 3, col_ = sub_ & 7;  \
        cp16(uV + (BI) * 18432 + pl_ * 9216 + row_ * 144 + col_ * 16,          \
             (pl_ ? vsl : vsh) + (size_t)row_ * NPIX + (K0) + col_ * 8);       \
    }                                                                          \
} while (0)

__global__ __launch_bounds__(256)
void flash_attn_mma(const uint16_t* __restrict__ QTh, const uint16_t* __restrict__ QTl,
                    const uint16_t* __restrict__ KTh, const uint16_t* __restrict__ KTl,
                    const uint16_t* __restrict__ Vh,  const uint16_t* __restrict__ Vl,
                    uint16_t* __restrict__ AOTh, uint16_t* __restrict__ AOTl)
{
    extern __shared__ char smc[];
    const uint32_t base = smem_u32(smc);
    const uint32_t uQ = base;
    const uint32_t uK = base + 18432;
    const uint32_t uV = base + 55296;
    float* sS = (float*)(smc + 18432);
    float* sL = (float*)(smc + 18432 + 17408);
    float* em = (float*)(smc + 18432 + 17664);
    float* el = (float*)(smc + 18432 + 18176);

    const int t    = threadIdx.x;
    const int warp = t >> 5, lane = t & 31;
    const int wm   = warp & 3, wn = warp >> 2;
    const int q0   = blockIdx.x * 64;
    const int bh   = blockIdx.y;
    const int b    = bh >> 3, h = bh & 7;

    const uint16_t* qsh = QTh + ((size_t)b * NPIX + q0) * INNER + h * 64;
    const uint16_t* qsl = QTl + ((size_t)b * NPIX + q0) * INNER + h * 64;
    const uint16_t* ksh = KTh + (size_t)b * NPIX * INNER + h * 64;
    const uint16_t* ksl = KTl + (size_t)b * NPIX * INNER + h * 64;
    const uint16_t* vsh = Vh + ((size_t)b * INNER + h * 64) * NPIX;
    const uint16_t* vsl = Vl + ((size_t)b * INNER + h * 64) * NPIX;

    const int arow  = lane & 15;
    const int acolb = (lane >> 4) * 16;
    const int brow  = (lane & 7) + ((lane >> 4) << 3);
    const int bcolb = ((lane >> 3) & 1) * 16;

    FA_FILLQ(); FA_FILLK(0, 0); FA_FILLV(0, 0); CP_COMMIT();
    FA_FILLK(64, 1); FA_FILLV(64, 1); CP_COMMIT();

    float accO[8][4] = {};
    float m0 = -1e30f, m1 = -1e30f, l0 = 0.f, l1 = 0.f;

    for (int kt = 0; kt < 16; kt++) {
        if (kt < 15) { CP_WAIT1(); } else { CP_WAIT0(); }
        __syncthreads();
        const uint32_t uKb = uK + (kt & 1) * 18432;
        const uint32_t uVb = uV + (kt & 1) * 18432;

        float s[4][4] = {};
        #pragma unroll
        for (int ks = 0; ks < 4; ks++) {
            const int kbyte = ks * 32;
            uint32_t ah[4], al[4], bhv[2][4], blv[2][4];
            {
                uint32_t off = (uint32_t)((wm * 16 + arow) * ASTR) * 2 + kbyte + acolb;
                ldmx4(ah, uQ + off);
                ldmx4(al, uQ + 9216 + off);
            }
            #pragma unroll
            for (int nt2 = 0; nt2 < 2; nt2++) {
                uint32_t off = (uint32_t)((wn * 32 + nt2 * 16 + brow) * ASTR) * 2
                             + kbyte + bcolb;
                ldmx4(bhv[nt2], uKb + off);
                ldmx4(blv[nt2], uKb + 9216 + off);
            }
            #pragma unroll
            for (int nt = 0; nt < 4; nt++) {
                uint32_t b0h = bhv[nt >> 1][(nt & 1) * 2];
                uint32_t b1h = bhv[nt >> 1][(nt & 1) * 2 + 1];
                uint32_t b0l = blv[nt >> 1][(nt & 1) * 2];
                uint32_t b1l = blv[nt >> 1][(nt & 1) * 2 + 1];
                mma_bf16(s[nt], ah, b0h, b1h);
                mma_bf16(s[nt], ah, b0l, b1l);
                mma_bf16(s[nt], al, b0h, b1h);
            }
        }

        float tm0 = -1e30f, tm1 = -1e30f;
        #pragma unroll
        for (int nt = 0; nt < 4; nt++) {
            tm0 = fmaxf(tm0, fmaxf(s[nt][0], s[nt][1]));
            tm1 = fmaxf(tm1, fmaxf(s[nt][2], s[nt][3]));
        }
        tm0 = fmaxf(tm0, __shfl_xor_sync(0xffffffffu, tm0, 1));
        tm0 = fmaxf(tm0, __shfl_xor_sync(0xffffffffu, tm0, 2));
        tm1 = fmaxf(tm1, __shfl_xor_sync(0xffffffffu, tm1, 1));
        tm1 = fmaxf(tm1, __shfl_xor_sync(0xffffffffu, tm1, 2));
        float mn0 = fmaxf(m0, tm0), mn1 = fmaxf(m1, tm1);
        float f0 = __expf(m0 - mn0), f1 = __expf(m1 - mn1);
        float sum0 = 0.f, sum1 = 0.f;
        #pragma unroll
        for (int nt = 0; nt < 4; nt++) {
            s[nt][0] = __expf(s[nt][0] - mn0);
            s[nt][1] = __expf(s[nt][1] - mn0);
            s[nt][2] = __expf(s[nt][2] - mn1);
            s[nt][3] = __expf(s[nt][3] - mn1);
            sum0 += s[nt][0] + s[nt][1];
            sum1 += s[nt][2] + s[nt][3];
        }
        sum0 += __shfl_xor_sync(0xffffffffu, sum0, 1);
        sum0 += __shfl_xor_sync(0xffffffffu, sum0, 2);
        sum1 += __shfl_xor_sync(0xffffffffu, sum1, 1);
        sum1 += __shfl_xor_sync(0xffffffffu, sum1, 2);
        l0 = l0 * f0 + sum0; l1 = l1 * f1 + sum1;
        m0 = mn0; m1 = mn1;
        #pragma unroll
        for (int nt = 0; nt < 8; nt++) {
            accO[nt][0] *= f0; accO[nt][1] *= f0;
            accO[nt][2] *= f1; accO[nt][3] *= f1;
        }

        uint32_t pfh[2][4], pfl[2][4];
        #pragma unroll
        for (int kc = 0; kc < 2; kc++) {
            packsplit2(s[2 * kc][0],     s[2 * kc][1],     pfh[kc][0], pfl[kc][0]);
            packsplit2(s[2 * kc][2],     s[2 * kc][3],     pfh[kc][1], pfl[kc][1]);
            packsplit2(s[2 * kc + 1][0], s[2 * kc + 1][1], pfh[kc][2], pfl[kc][2]);
            packsplit2(s[2 * kc + 1][2], s[2 * kc + 1][3], pfh[kc][3], pfl[kc][3]);
        }

        #pragma unroll
        for (int kc = 0; kc < 2; kc++) {
            const int kbyte = wn * 64 + kc * 32;
            uint32_t bhv[4][4], blv[4][4];
            #pragma unroll
            for (int nt2 = 0; nt2 < 4; nt2++) {
                uint32_t off = (uint32_t)((nt2 * 16 + brow) * ASTR) * 2 + kbyte + bcolb;
                ldmx4(bhv[nt2], uVb + off);
                ldmx4(blv[nt2], uVb + 9216 + off);
            }
            #pragma unroll
            for (int nt = 0; nt < 8; nt++) {
                uint32_t b0h = bhv[nt >> 1][(nt & 1) * 2];
                uint32_t b1h = bhv[nt >> 1][(nt & 1) * 2 + 1];
                uint32_t b0l = blv[nt >> 1][(nt & 1) * 2];
                uint32_t b1l = blv[nt >> 1][(nt & 1) * 2 + 1];
                mma_bf16(accO[nt], pfh[kc], b0h, b1h);
                mma_bf16(accO[nt], pfh[kc], b0l, b1l);
                mma_bf16(accO[nt], pfl[kc], b0h, b1h);
            }
        }
        __syncthreads();
        if (kt < 14) {
            FA_FILLK((kt + 2) * 64, kt & 1);
            FA_FILLV((kt + 2) * 64, kt & 1);
            CP_COMMIT();
        }
    }

    {
        int r0 = wm * 16 + (lane >> 2);
        if ((lane & 3) == 0) {
            em[wn * 64 + r0] = m0;     el[wn * 64 + r0] = l0;
            em[wn * 64 + r0 + 8] = m1; el[wn * 64 + r0 + 8] = l1;
        }
    }
    __syncthreads();
    {
        int r0 = wm * 16 + (lane >> 2);
        float mo0 = em[(wn ^ 1) * 64 + r0],     lo0 = el[(wn ^ 1) * 64 + r0];
        float mo1 = em[(wn ^ 1) * 64 + r0 + 8], lo1 = el[(wn ^ 1) * 64 + r0 + 8];
        float M0 = fmaxf(m0, mo0), M1 = fmaxf(m1, mo1);
        float myf0 = __expf(m0 - M0), myf1 = __expf(m1 - M1);
        float L0 = l0 * myf0 + lo0 * __expf(mo0 - M0);
        float L1 = l1 * myf1 + lo1 * __expf(mo1 - M1);
        if (wn == 0) {
            #pragma unroll
            for (int nt = 0; nt < 8; nt++) {
                int col = nt * 8 + (lane & 3) * 2;
                *(float2*)(sS + r0 * 68 + col) =
                    make_float2(accO[nt][0] * myf0, accO[nt][1] * myf0);
                *(float2*)(sS + (r0 + 8) * 68 + col) =
                    make_float2(accO[nt][2] * myf1, accO[nt][3] * myf1);
            }
            if ((lane & 3) == 0) { sL[r0] = L0; sL[r0 + 8] = L1; }
        }
        __syncthreads();
        if (wn == 1) {
            #pragma unroll
            for (int nt = 0; nt < 8; nt++) {
                int col = nt * 8 + (lane & 3) * 2;
                float2 v0 = *(float2*)(sS + r0 * 68 + col);
                float2 v1 = *(float2*)(sS + (r0 + 8) * 68 + col);
                v0.x += accO[nt][0] * myf0; v0.y += accO[nt][1] * myf0;
                v1.x += accO[nt][2] * myf1; v1.y += accO[nt][3] * myf1;
                *(float2*)(sS + r0 * 68 + col) = v0;
                *(float2*)(sS + (r0 + 8) * 68 + col) = v1;
            }
        }
    }
    __syncthreads();
    {
        uint16_t* aoh = AOTh + ((size_t)b * NPIX + q0) * INNER + h * 64;
        uint16_t* aol = AOTl + ((size_t)b * NPIX + q0) * INNER + h * 64;
        for (int idx = t; idx < 4096; idx += 256) {
            int q = idx >> 6, d = idx & 63;
            float v = sS[q * 68 + d] / sL[q];
            float g = 0.5f * v * (1.f + erff(v * 0.70710678118654752f));
            __nv_bfloat16 hh, ll; split2(g, hh, ll);
            size_t o = (size_t)q * INNER + d;
            aoh[o] = u16(hh); aol[o] = u16(ll);
        }
    }
}

// ---------------------------------------------------------------------------
extern "C" void kernel_launch(void* const* d_in, const int* in_sizes, int n_in,
                              void* d_out, int out_size)
{
    const float* x    = (const float*)d_in[0];
    const float* Wq   = (const float*)d_in[1];
    const float* Wkv  = (const float*)d_in[2];
    const float* Wout = (const float*)d_in[3];
    const float* bout = (const float*)d_in[4];
    float* out = (float*)d_out;

    uint16_t *wqh, *wql, *wkvh, *wkvl, *woh, *wol;
    uint16_t *xth, *xtl, *qth, *qtl, *kth, *ktl, *vh, *vl, *aoh, *aol;
    cudaGetSymbolAddress((void**)&wqh,  g_Wq_h);  cudaGetSymbolAddress((void**)&wql,  g_Wq_l);
    cudaGetSymbolAddress((void**)&wkvh, g_Wkv_h); cudaGetSymbolAddress((void**)&wkvl, g_Wkv_l);
    cudaGetSymbolAddress((void**)&woh,  g_Wo_h);  cudaGetSymbolAddress((void**)&wol,  g_Wo_l);
    cudaGetSymbolAddress((void**)&xth,  g_XT_h);  cudaGetSymbolAddress((void**)&xtl,  g_XT_l);
    cudaGetSymbolAddress((void**)&qth,  g_QT_h);  cudaGetSymbolAddress((void**)&qtl,  g_QT_l);
    cudaGetSymbolAddress((void**)&kth,  g_KT_h);  cudaGetSymbolAddress((void**)&ktl,  g_KT_l);
    cudaGetSymbolAddress((void**)&vh,   g_V_h);   cudaGetSymbolAddress((void**)&vl,   g_V_l);
    cudaGetSymbolAddress((void**)&aoh,  g_AOT_h); cudaGetSymbolAddress((void**)&aol,  g_AOT_l);

    dim3 blk(256);

    // 0) weight planes (Wq scale-folded; Wkv tap-major permuted) + XT
    split_planes<<<(INNER * C_IN + 255) / 256, blk>>>(Wq, wqh, wql, INNER * C_IN, 0.125f);
    split_wkv_perm<<<(MKV * KCONV + 255) / 256, blk>>>(Wkv, wkvh, wkvl);
    split_planes<<<(C_IN * INNER + 255) / 256, blk>>>(Wout, woh, wol, C_IN * INNER, 1.f);
    transXT<<<dim3(32, 8, BATCH), blk>>>(x, xth, xtl);

    // 1) fused conv3x3 (halo slab) + Q projection, one launch
    cudaFuncSetAttribute(conv_q, cudaFuncAttributeMaxDynamicSharedMemorySize, CV_SMEM);
    conv_q<<<dim3(16, 12, BATCH), blk, CV_SMEM>>>(
        wkvh, wkvl, wqh, wql, xth, xtl, kth, ktl, vh, vl, qth, qtl);

    // 2) attention + GELU -> AOT planes (register-resident FA2)
    cudaFuncSetAttribute(flash_attn_mma, cudaFuncAttributeMaxDynamicSharedMemorySize, FA_SMEM);
    flash_attn_mma<<<dim3(16, BATCH * HEADS), blk, FA_SMEM>>>(
        qth, qtl, kth, ktl, vh, vl, aoh, aol);

    // 3) out = Wout · gelu_attn + bout  (K=512, 8 panels)
    cudaFuncSetAttribute(gemm_out, cudaFuncAttributeMaxDynamicSharedMemorySize, GP_SMEM);
    gemm_out<<<dim3(16, 2, BATCH), blk, GP_SMEM>>>(
        woh, wol, aoh, aol, INNER, 8, out, bout, 256);
}